// round 6
// baseline (speedup 1.0000x reference)
#include <cuda_runtime.h>

typedef unsigned long long ULL;

// ---------------- f32x2 helpers (Blackwell packed fp32) ----------------
__device__ __forceinline__ ULL pk2(float a, float b) {
    ULL r; asm("mov.b64 %0, {%1, %2};" : "=l"(r) : "f"(a), "f"(b)); return r;
}
__device__ __forceinline__ void upk2(ULL v, float& a, float& b) {
    asm("mov.b64 {%0, %1}, %2;" : "=f"(a), "=f"(b) : "l"(v));
}
#define FMA2(acc, a, b) asm("fma.rn.f32x2 %0, %1, %2, %0;" : "+l"(acc) : "l"(a), "l"(b))

// ---------------- problem constants ----------------
constexpr int B_   = 4096;
constexpr int T_   = 128;
constexpr int I_   = 28;
constexpr int O_   = 10;
constexpr int RPB  = 16;           // batch rows per block
constexpr int NBLK = B_ / RPB;     // 256 blocks (2 CTAs co-resident on most SMs)
constexpr int NTHR = 128;          // 64 units x 2 row-groups

constexpr int K2HH = 32;           // 64 hidden k -> 32 pairs
constexpr int K2IH = 14;           // 28 input  k -> 14 pairs
constexpr int K2T  = K2HH + K2IH;  // 46
constexpr int WROW = 512;          // floats per k2 row of weight pairs: 256 gates * 2
constexpr int RPAD = 36;           // floats per k2 row of h/x pairs: 16 rows * 2 + 4 pad (mult of 4)

// shared memory layout (floats), per CTA
constexpr int WS_ELE = K2T * WROW;              // 23552
constexpr int HP_OFF = WS_ELE;                  // hP[2][K2HH][RPAD]  double buffer
constexpr int XP_OFF = HP_OFF + 2 * K2HH * RPAD; // xP[2][K2IH][RPAD] double buffer
constexpr int SM_FLOATS = XP_OFF + 2 * K2IH * RPAD;   // 26864 floats = 107.5 KB

// ---------------- activations (accurate, exp-based; identical math since R1) ----------------
__device__ __forceinline__ float sigf(float x) {
    return __fdividef(1.0f, 1.0f + __expf(-x));
}
__device__ __forceinline__ float tanh_(float x) {
    float ax = fabsf(x);
    float e  = __expf(-2.0f * ax);
    float r  = __fdividef(1.0f - e, 1.0f + e);
    return copysignf(r, x);
}

__global__ void __launch_bounds__(NTHR, 2) lstm_fused(
    const float* __restrict__ x,     // [B, T, I]
    const float* __restrict__ Wih,   // [4H, I]
    const float* __restrict__ Whh,   // [4H, H]
    const float* __restrict__ bih,   // [4H]
    const float* __restrict__ bhh,   // [4H]
    const float* __restrict__ Wout,  // [O, H]
    const float* __restrict__ bout,  // [O]
    float* __restrict__ out)         // [B, O]
{
    extern __shared__ float sm[];
    float* Ws = sm;            // weight pairs: Ws[k2][ (j*4+q)*2 + (k&1) ]
    float* hP = sm + HP_OFF;   // h pairs:     hP[buf][k2][2*r + (k&1)]
    float* xP = sm + XP_OFF;   // x pairs

    const int tid   = threadIdx.x;
    const int j     = tid & 63;   // hidden unit owned by this thread
    const int ty    = tid >> 6;   // row group (0..1), 8 rows each
    const int rbase = ty * 8;
    const int row0  = blockIdx.x * RPB;

    // ---- stage weights into SMEM as even/odd-k pairs, gate-interleaved ----
    for (int idx = tid; idx < 256 * 64; idx += NTHR) {        // Whh: idx = g*64 + k
        int g = idx >> 6, k = idx & 63;
        Ws[(k >> 1) * WROW + ((g & 63) * 4 + (g >> 6)) * 2 + (k & 1)] = Whh[idx];
    }
    for (int idx = tid; idx < 256 * 28; idx += NTHR) {        // Wih: idx = g*28 + k
        int g = idx / 28, k = idx - g * 28;
        Ws[(K2HH + (k >> 1)) * WROW + ((g & 63) * 4 + (g >> 6)) * 2 + (k & 1)] = Wih[idx];
    }
    for (int idx = tid; idx < 2 * K2HH * RPAD; idx += NTHR) hP[idx] = 0.0f;

    // biases (combined)
    const float b0 = bih[j]       + bhh[j];
    const float b1 = bih[64 + j]  + bhh[64 + j];
    const float b2 = bih[128 + j] + bhh[128 + j];
    const float b3 = bih[192 + j] + bhh[192 + j];

    // ---- preload x for t = 0 into buffer 0 ----  (RPB*I = 448 elements, 128 threads)
    #pragma unroll
    for (int u = 0; u < 4; ++u) {
        int e = u * NTHR + tid;
        if (e < RPB * I_) {
            int r = e / 28, i2 = e - r * 28;
            xP[(i2 >> 1) * RPAD + 2 * r + (i2 & 1)] = x[(row0 + r) * (T_ * I_) + 0 * I_ + i2];
        }
    }
    __syncthreads();

    float creg[8];
    #pragma unroll
    for (int r = 0; r < 8; ++r) creg[r] = 0.0f;

    // =================== time loop (one barrier per step) ===================
    for (int t = 0; t < T_; ++t) {
        // prefetch x for t+1 (LDG latency overlaps this step's compute)
        float xn[4];
        const bool pf = (t + 1 < T_);
        if (pf) {
            #pragma unroll
            for (int u = 0; u < 4; ++u) {
                int e = u * NTHR + tid;
                int e2 = (e < RPB * I_) ? e : 0;      // branch-free clamp
                int r = e2 / 28, i2 = e2 - r * 28;
                xn[u] = x[(row0 + r) * (T_ * I_) + (t + 1) * I_ + i2];
            }
        }

        const float* xb = xP + (t & 1) * K2IH * RPAD;
        const float* hb = hP + (t & 1) * K2HH * RPAD;   // read buffer

        // accumulators: acc[row][gate] = (sum over even k, sum over odd k)
        ULL acc[8][4];
        #pragma unroll
        for (int r = 0; r < 8; ++r)
            #pragma unroll
            for (int q = 0; q < 4; ++q)
                acc[r][q] = 0ULL;

        // ---- recurrent part: k2 over hidden-unit pairs ----
        #pragma unroll 8
        for (int k2 = 0; k2 < K2HH; ++k2) {
            const float* wp = Ws + k2 * WROW + j * 8;
            const ulonglong2 wA = *reinterpret_cast<const ulonglong2*>(wp);      // gates i,f
            const ulonglong2 wB = *reinterpret_cast<const ulonglong2*>(wp + 4);  // gates g,o
            const ULL* hp = reinterpret_cast<const ULL*>(hb + k2 * RPAD + 2 * rbase);
            const ULL h0 = hp[0], h1 = hp[1], h2 = hp[2], h3 = hp[3];
            const ULL h4 = hp[4], h5 = hp[5], h6 = hp[6], h7 = hp[7];
            FMA2(acc[0][0], h0, wA.x); FMA2(acc[0][1], h0, wA.y); FMA2(acc[0][2], h0, wB.x); FMA2(acc[0][3], h0, wB.y);
            FMA2(acc[1][0], h1, wA.x); FMA2(acc[1][1], h1, wA.y); FMA2(acc[1][2], h1, wB.x); FMA2(acc[1][3], h1, wB.y);
            FMA2(acc[2][0], h2, wA.x); FMA2(acc[2][1], h2, wA.y); FMA2(acc[2][2], h2, wB.x); FMA2(acc[2][3], h2, wB.y);
            FMA2(acc[3][0], h3, wA.x); FMA2(acc[3][1], h3, wA.y); FMA2(acc[3][2], h3, wB.x); FMA2(acc[3][3], h3, wB.y);
            FMA2(acc[4][0], h4, wA.x); FMA2(acc[4][1], h4, wA.y); FMA2(acc[4][2], h4, wB.x); FMA2(acc[4][3], h4, wB.y);
            FMA2(acc[5][0], h5, wA.x); FMA2(acc[5][1], h5, wA.y); FMA2(acc[5][2], h5, wB.x); FMA2(acc[5][3], h5, wB.y);
            FMA2(acc[6][0], h6, wA.x); FMA2(acc[6][1], h6, wA.y); FMA2(acc[6][2], h6, wB.x); FMA2(acc[6][3], h6, wB.y);
            FMA2(acc[7][0], h7, wA.x); FMA2(acc[7][1], h7, wA.y); FMA2(acc[7][2], h7, wB.x); FMA2(acc[7][3], h7, wB.y);
        }
        // ---- input part: k2 over input pairs ----
        #pragma unroll 7
        for (int k2 = 0; k2 < K2IH; ++k2) {
            const float* wp = Ws + (K2HH + k2) * WROW + j * 8;
            const ulonglong2 wA = *reinterpret_cast<const ulonglong2*>(wp);
            const ulonglong2 wB = *reinterpret_cast<const ulonglong2*>(wp + 4);
            const ULL* hp = reinterpret_cast<const ULL*>(xb + k2 * RPAD + 2 * rbase);
            const ULL h0 = hp[0], h1 = hp[1], h2 = hp[2], h3 = hp[3];
            const ULL h4 = hp[4], h5 = hp[5], h6 = hp[6], h7 = hp[7];
            FMA2(acc[0][0], h0, wA.x); FMA2(acc[0][1], h0, wA.y); FMA2(acc[0][2], h0, wB.x); FMA2(acc[0][3], h0, wB.y);
            FMA2(acc[1][0], h1, wA.x); FMA2(acc[1][1], h1, wA.y); FMA2(acc[1][2], h1, wB.x); FMA2(acc[1][3], h1, wB.y);
            FMA2(acc[2][0], h2, wA.x); FMA2(acc[2][1], h2, wA.y); FMA2(acc[2][2], h2, wB.x); FMA2(acc[2][3], h2, wB.y);
            FMA2(acc[3][0], h3, wA.x); FMA2(acc[3][1], h3, wA.y); FMA2(acc[3][2], h3, wB.x); FMA2(acc[3][3], h3, wB.y);
            FMA2(acc[4][0], h4, wA.x); FMA2(acc[4][1], h4, wA.y); FMA2(acc[4][2], h4, wB.x); FMA2(acc[4][3], h4, wB.y);
            FMA2(acc[5][0], h5, wA.x); FMA2(acc[5][1], h5, wA.y); FMA2(acc[5][2], h5, wB.x); FMA2(acc[5][3], h5, wB.y);
            FMA2(acc[6][0], h6, wA.x); FMA2(acc[6][1], h6, wA.y); FMA2(acc[6][2], h6, wB.x); FMA2(acc[6][3], h6, wB.y);
            FMA2(acc[7][0], h7, wA.x); FMA2(acc[7][1], h7, wA.y); FMA2(acc[7][2], h7, wB.x); FMA2(acc[7][3], h7, wB.y);
        }

        // ---- elementwise LSTM cell update (fold even/odd lanes, add bias) ----
        float hnew[8];
        #pragma unroll
        for (int r = 0; r < 8; ++r) {
            float e0, o0, e1, o1, e2, o2, e3, o3;
            upk2(acc[r][0], e0, o0);
            upk2(acc[r][1], e1, o1);
            upk2(acc[r][2], e2, o2);
            upk2(acc[r][3], e3, o3);
            float gi = (e0 + o0) + b0;
            float gf = (e1 + o1) + b1;
            float gg = (e2 + o2) + b2;
            float go = (e3 + o3) + b3;
            float iv = sigf(gi), fv = sigf(gf), gv = tanh_(gg), ov = sigf(go);
            creg[r] = fv * creg[r] + iv * gv;
            hnew[r] = ov * tanh_(creg[r]);
        }

        // write new h into the OTHER buffer (pair layout); stage next x tile.
        {
            float* hd = hP + ((t + 1) & 1) * K2HH * RPAD + (j >> 1) * RPAD + (j & 1);
            #pragma unroll
            for (int r = 0; r < 8; ++r) hd[2 * (rbase + r)] = hnew[r];
        }
        if (pf) {
            float* xb2 = xP + ((t + 1) & 1) * K2IH * RPAD;
            #pragma unroll
            for (int u = 0; u < 4; ++u) {
                int e = u * NTHR + tid;
                if (e < RPB * I_) {
                    int r = e / 28, i2 = e - r * 28;
                    xb2[(i2 >> 1) * RPAD + 2 * r + (i2 & 1)] = xn[u];
                }
            }
        }
        __syncthreads();   // writes visible before next step reads them
    }

    // ---- final projection: out[b][o] = h_T[b] . Wout[o] + bout[o] ----
    const float* hf = hP + (T_ & 1) * K2HH * RPAD;
    for (int idx = tid; idx < RPB * O_; idx += NTHR) {
        int r = idx / O_, o = idx - r * O_;
        float s = bout[o];
        #pragma unroll
        for (int k = 0; k < 64; ++k)
            s += hf[(k >> 1) * RPAD + 2 * r + (k & 1)] * Wout[o * 64 + k];
        out[(row0 + r) * O_ + o] = s;
    }
}

extern "C" void kernel_launch(void* const* d_in, const int* in_sizes, int n_in,
                              void* d_out, int out_size)
{
    const float* x    = (const float*)d_in[0];
    const float* Wih  = (const float*)d_in[1];
    const float* Whh  = (const float*)d_in[2];
    const float* bih  = (const float*)d_in[3];
    const float* bhh  = (const float*)d_in[4];
    const float* Wout = (const float*)d_in[5];
    const float* bout = (const float*)d_in[6];
    float* out = (float*)d_out;

    const size_t smem = (size_t)SM_FLOATS * sizeof(float);  // ~107.5 KB per CTA
    cudaFuncSetAttribute(lstm_fused, cudaFuncAttributeMaxDynamicSharedMemorySize, (int)smem);
    lstm_fused<<<NBLK, NTHR, smem>>>(x, Wih, Whh, bih, bhh, Wout, bout, out);
}